// round 11
// baseline (speedup 1.0000x reference)
#include <cuda_runtime.h>
#include <cstdint>

// Problem constants
#define NB   4
#define SEQ  1024
#define NH   16
#define DH   64
#define DM   1024
#define MROWS (NB * SEQ)

// Pre-split tf32 hi/lo copies of the GEMM inputs.
__device__ float g_xh[MROWS * DM], g_xl[MROWS * DM];
__device__ float g_wh[3 * DM * DM], g_wl[3 * DM * DM];

// Pre-split tf32 hi/lo Q/K ([B,H,S,DH], paired d-permutation) and V hi only
// ([B,H,DH,S] transposed, paired s-permutation).
__device__ float g_qh[NB * NH * SEQ * DH];
__device__ float g_ql[NB * NH * SEQ * DH];
__device__ float g_kh[NB * NH * SEQ * DH];
__device__ float g_kl[NB * NH * SEQ * DH];
__device__ float g_vh[NB * NH * SEQ * DH];

__device__ __forceinline__ int perm8(int x) { return ((x & 3) << 1) | ((x >> 2) & 1); }

__device__ __forceinline__ float to_tf32(float x) {
    unsigned u;
    asm("cvt.rna.tf32.f32 %0, %1;" : "=r"(u) : "f"(x));
    return __uint_as_float(u);
}
__device__ __forceinline__ void split_tf32(float x, float& hi, float& lo) {
    hi = to_tf32(x);
    lo = to_tf32(x - hi);
}
__device__ __forceinline__ void mma_tf32(float* c, const unsigned* a, const unsigned* b) {
    asm volatile(
        "mma.sync.aligned.m16n8k8.row.col.f32.tf32.tf32.f32 "
        "{%0,%1,%2,%3},{%4,%5,%6,%7},{%8,%9},{%0,%1,%2,%3};"
        : "+f"(c[0]), "+f"(c[1]), "+f"(c[2]), "+f"(c[3])
        : "r"(a[0]), "r"(a[1]), "r"(a[2]), "r"(a[3]), "r"(b[0]), "r"(b[1]));
}
__device__ __forceinline__ float warpMax(float v) {
#pragma unroll
    for (int o = 16; o > 0; o >>= 1) v = fmaxf(v, __shfl_xor_sync(0xffffffffu, v, o));
    return v;
}
__device__ __forceinline__ float warpSum(float v) {
#pragma unroll
    for (int o = 16; o > 0; o >>= 1) v += __shfl_xor_sync(0xffffffffu, v, o);
    return v;
}

#define CP_COMMIT() asm volatile("cp.async.commit_group;")
#define CP_WAIT(N)  asm volatile("cp.async.wait_group %0;" :: "n"(N))

__device__ __forceinline__ void cp16(float* dst, const float* src) {
    uint32_t a = (uint32_t)__cvta_generic_to_shared(dst);
    asm volatile("cp.async.cg.shared.global [%0], [%1], 16;" :: "r"(a), "l"(src));
}

// ---------------------------------------------------------------------------
// Pre-split X, Wq, Wk, Wv into tf32 hi/lo device arrays. Memory-bound.
// ---------------------------------------------------------------------------
__global__ __launch_bounds__(256) void presplit_kernel(
    const float* __restrict__ X, const float* __restrict__ Wq,
    const float* __restrict__ Wk, const float* __restrict__ Wv) {
    const size_t NX = (size_t)MROWS * DM / 4;
    const size_t NW = (size_t)DM * DM / 4;
    size_t i = (size_t)blockIdx.x * 256 + threadIdx.x;
    const float4* src;
    float4 *dh, *dl;
    size_t j;
    if (i < NX)               { src = (const float4*)X;  dh = (float4*)g_xh;      dl = (float4*)g_xl;      j = i; }
    else if (i < NX + NW)     { src = (const float4*)Wq; dh = (float4*)g_wh;      dl = (float4*)g_wl;      j = i - NX; }
    else if (i < NX + 2 * NW) { src = (const float4*)Wk; dh = (float4*)g_wh + NW; dl = (float4*)g_wl + NW; j = i - NX - NW; }
    else                      { src = (const float4*)Wv; dh = (float4*)g_wh + 2 * NW; dl = (float4*)g_wl + 2 * NW; j = i - NX - 2 * NW; }
    float4 v = src[j];
    float4 hv, lv;
    split_tf32(v.x, hv.x, lv.x); split_tf32(v.y, hv.y, lv.y);
    split_tf32(v.z, hv.z, lv.z); split_tf32(v.w, hv.w, lv.w);
    dh[j] = hv;
    dl[j] = lv;
}

// ---------------------------------------------------------------------------
// QKV projection, 3xTF32. 512 threads, 16 warps (4x4 of 32x32 warp tiles),
// CTA tile 128x128, k-stage 16, cp.async double-buffer (75.8 KB smem).
// ---------------------------------------------------------------------------
constexpr int PKS  = 16;             // k-floats per stage
constexpr int PXS  = 20;             // X row stride (banks (20g+t)%32 all distinct)
constexpr int PWS  = 136;            // W row stride (≡8 mod 32)
constexpr int XSTG = 128 * PXS;      // 2560
constexpr int WSTG = PKS * PWS;      // 2176
constexpr int STG  = 2 * XSTG + 2 * WSTG;   // 9472 floats per stage
constexpr int PROJ_SMEM_FLOATS = 2 * STG;   // 75.8 KB

__device__ __forceinline__ void proj_stage(float* s, const float* xh, const float* xl,
                                           const float* wh, const float* wl,
                                           int m0, int n0, int k0, int tid) {
    float* Xh = s;
    float* Xl = s + XSTG;
    float* Wh = s + 2 * XSTG;
    float* Wl = s + 2 * XSTG + WSTG;
    {   // X tile 128x16
        const int r = tid >> 2, c = (tid & 3) << 2;
        const size_t go = (size_t)(m0 + r) * DM + k0 + c;
        cp16(Xh + r * PXS + c, xh + go);
        cp16(Xl + r * PXS + c, xl + go);
    }
    {   // W tile 16x128
        const int r = tid >> 5, c = (tid & 31) << 2;
        const size_t go = (size_t)(k0 + r) * DM + n0 + c;
        cp16(Wh + r * PWS + c, wh + go);
        cp16(Wl + r * PWS + c, wl + go);
    }
}

__global__ __launch_bounds__(512) void qkv_proj_tc(
    const float* __restrict__ bq, const float* __restrict__ bk,
    const float* __restrict__ bv) {
    extern __shared__ float psm[];

    const int z = blockIdx.z;
    const float* wh = g_wh + (size_t)z * DM * DM;
    const float* wl = g_wl + (size_t)z * DM * DM;
    const float* bias = (z == 0) ? bq : (z == 1) ? bk : bv;
    float* outh = (z == 0) ? g_qh : (z == 1) ? g_kh : g_vh;
    float* outl = (z == 0) ? g_ql : g_kl;     // unused for V
    const bool isV = (z == 2);

    const int tid = threadIdx.x;
    const int warp = tid >> 5, lane = tid & 31;
    const int g = lane >> 2, t = lane & 3;
    const int wm = (warp >> 2) * 32, wn = (warp & 3) * 32;
    const int m0 = blockIdx.y * 128, n0 = blockIdx.x * 128;

    float acc[2][4][4] = {};

    proj_stage(psm, g_xh, g_xl, wh, wl, m0, n0, 0, tid);
    CP_COMMIT();

    for (int kb = 0; kb < DM / PKS; ++kb) {
        CP_WAIT(0);
        __syncthreads();
        if (kb + 1 < DM / PKS) {
            proj_stage(psm + ((kb + 1) & 1) * STG, g_xh, g_xl, wh, wl,
                       m0, n0, (kb + 1) * PKS, tid);
            CP_COMMIT();
        }
        const float* Xh = psm + (kb & 1) * STG;
        const float* Xl = Xh + XSTG;
        const float* Wh = Xh + 2 * XSTG;
        const float* Wl = Xh + 2 * XSTG + WSTG;

#pragma unroll
        for (int ks = 0; ks < 2; ++ks) {
            unsigned ah[2][4], al[2][4], bh[4][2], bl[4][2];
#pragma unroll
            for (int i = 0; i < 2; ++i) {
                const int off = (wm + 16 * i + g) * PXS + 8 * ks + t;
                ah[i][0] = __float_as_uint(Xh[off]);
                ah[i][1] = __float_as_uint(Xh[off + 8 * PXS]);
                ah[i][2] = __float_as_uint(Xh[off + 4]);
                ah[i][3] = __float_as_uint(Xh[off + 8 * PXS + 4]);
                al[i][0] = __float_as_uint(Xl[off]);
                al[i][1] = __float_as_uint(Xl[off + 8 * PXS]);
                al[i][2] = __float_as_uint(Xl[off + 4]);
                al[i][3] = __float_as_uint(Xl[off + 8 * PXS + 4]);
            }
#pragma unroll
            for (int j = 0; j < 4; ++j) {
                const int off = (8 * ks + t) * PWS + wn + 8 * j + g;
                bh[j][0] = __float_as_uint(Wh[off]);
                bh[j][1] = __float_as_uint(Wh[off + 4 * PWS]);
                bl[j][0] = __float_as_uint(Wl[off]);
                bl[j][1] = __float_as_uint(Wl[off + 4 * PWS]);
            }
#pragma unroll
            for (int i = 0; i < 2; ++i)
#pragma unroll
                for (int j = 0; j < 4; ++j)
                    mma_tf32(acc[i][j], ah[i], bh[j]);
#pragma unroll
            for (int i = 0; i < 2; ++i)
#pragma unroll
                for (int j = 0; j < 4; ++j)
                    mma_tf32(acc[i][j], al[i], bh[j]);
#pragma unroll
            for (int i = 0; i < 2; ++i)
#pragma unroll
                for (int j = 0; j < 4; ++j)
                    mma_tf32(acc[i][j], ah[i], bl[j]);
        }
    }

    // epilogue: + bias, split, scatter into permuted layouts
#pragma unroll
    for (int j = 0; j < 4; ++j) {
        const int n = n0 + wn + 8 * j + 2 * t;
        const float b0v = bias[n], b1v = bias[n + 1];
        const int h = n >> 6, hd = n & 63;
        const int pd = (hd & ~7) | perm8(hd & 7);
#pragma unroll
        for (int i = 0; i < 2; ++i) {
            const int m = m0 + wm + 16 * i + g;
            const int bI = m >> 10, s = m & 1023;
            const int m2 = m + 8;
            const int bI2 = m2 >> 10, s2 = m2 & 1023;
            const float v0 = acc[i][j][0] + b0v;
            const float v1 = acc[i][j][1] + b1v;
            const float v2 = acc[i][j][2] + b0v;
            const float v3 = acc[i][j][3] + b1v;
            if (!isV) {
                float h0, l0, h1, l1, h2, l2, h3, l3;
                split_tf32(v0, h0, l0);
                split_tf32(v1, h1, l1);
                split_tf32(v2, h2, l2);
                split_tf32(v3, h3, l3);
                const size_t b1o = ((size_t)((bI * NH + h) * SEQ + s)) * DH;
                outh[b1o + pd] = h0;  outh[b1o + pd + 2] = h1;
                outl[b1o + pd] = l0;  outl[b1o + pd + 2] = l1;
                const size_t b2o = ((size_t)((bI2 * NH + h) * SEQ + s2)) * DH;
                outh[b2o + pd] = h2;  outh[b2o + pd + 2] = h3;
                outl[b2o + pd] = l2;  outl[b2o + pd + 2] = l3;
            } else {
                const int ps1 = (s & ~7) | perm8(s & 7);
                const int ps2 = (s2 & ~7) | perm8(s2 & 7);
                const size_t r0 = ((size_t)((bI * NH + h) * DH + hd)) * SEQ;
                const size_t r1 = ((size_t)((bI * NH + h) * DH + hd + 1)) * SEQ;
                outh[r0 + ps1] = to_tf32(v0);  outh[r1 + ps1] = to_tf32(v1);
                const size_t r0b = ((size_t)((bI2 * NH + h) * DH + hd)) * SEQ;
                const size_t r1b = ((size_t)((bI2 * NH + h) * DH + hd + 1)) * SEQ;
                outh[r0b + ps2] = to_tf32(v2);  outh[r1b + ps2] = to_tf32(v3);
            }
        }
    }
}

// ---------------------------------------------------------------------------
// Attention, 512 threads, cp.async double-buffer, 1 barrier/chunk.
// Phase 1: 3xTF32 QK^T (b-frags software-pipelined).
// Phase 2: Michelot sparsemax / softmax.  Phase 3: w(tf32) @ V(hi).
// ---------------------------------------------------------------------------
constexpr int TQ  = 32;
constexpr int CK  = 64;
constexpr int NCH = SEQ / CK;     // 16
constexpr int NT  = 512;
constexpr int APS = 72;
constexpr int SCP = 1032;
constexpr int KVSTG = CK * APS;
constexpr int ATTN_SMEM_FLOATS = TQ * SCP + 2 * TQ * APS + 4 * KVSTG;
constexpr float SCALE = 0.125f;

__device__ __forceinline__ void stage_cp2(float* dh, float* dl,
                                          const float* gh, const float* gl,
                                          int tid, int gstride) {
#pragma unroll
    for (int it = 0; it < 2; ++it) {
        const int idx = tid + 512 * it;
        const int r = idx >> 4, c = (idx & 15) << 2;
        const int so = r * APS + c;
        const size_t go = (size_t)r * gstride + c;
        cp16(dh + so, gh + go);
        cp16(dl + so, gl + go);
    }
}
__device__ __forceinline__ void stage_cp1(float* dh, const float* gh,
                                          int tid, int gstride) {
#pragma unroll
    for (int it = 0; it < 2; ++it) {
        const int idx = tid + 512 * it;
        const int r = idx >> 4, c = (idx & 15) << 2;
        cp16(dh + r * APS + c, gh + (size_t)r * gstride + c);
    }
}

__global__ __launch_bounds__(NT, 1) void attn_tc(const float* __restrict__ mask,
                                                 float* __restrict__ out) {
    extern __shared__ float sm[];
    float* sc  = sm;                    // [TQ][SCP]
    float* qsh = sm + TQ * SCP;         // [TQ][APS]
    float* qsl = qsh + TQ * APS;
    float* kv  = qsl + TQ * APS;

    float* kvH[2] = { kv, kv + 2 * KVSTG };
    float* kvL[2] = { kv + KVSTG, kv + 3 * KVSTG };

    const int tid = threadIdx.x;
    const int b = blockIdx.z, h = blockIdx.y;
    const int q0 = blockIdx.x * TQ;
    const int bh_i = b * NH + h;
    const float* Qh = g_qh + ((size_t)bh_i * SEQ + q0) * DH;
    const float* Ql = g_ql + ((size_t)bh_i * SEQ + q0) * DH;
    const float* Kh = g_kh + (size_t)bh_i * SEQ * DH;
    const float* Kl = g_kl + (size_t)bh_i * SEQ * DH;
    const float* Vh = g_vh + (size_t)bh_i * DH * SEQ;
    const float* mrow = mask + b * SEQ;

    const int warp = tid >> 5, lane = tid & 31;
    const int g = lane >> 2, t = lane & 3;
    const int wq = warp >> 3;
    const int wk = warp & 7;

    stage_cp2(kvH[0], kvL[0], Kh, Kl, tid, DH);
    CP_COMMIT();
    {
        const int e = tid << 2;
        const int qi = e >> 6, dd = e & 63;
        *(float4*)(qsh + qi * APS + dd) = *(const float4*)(Qh + e);
        *(float4*)(qsl + qi * APS + dd) = *(const float4*)(Ql + e);
    }
    __syncthreads();

    unsigned qah[8][4], qal[8][4];
#pragma unroll
    for (int ks = 0; ks < 8; ++ks) {
        const int off = (16 * wq + g) * APS + 8 * ks + 2 * t;
        float2 f0 = *(const float2*)(qsh + off);
        float2 f1 = *(const float2*)(qsh + off + 8 * APS);
        qah[ks][0] = __float_as_uint(f0.x);
        qah[ks][1] = __float_as_uint(f1.x);
        qah[ks][2] = __float_as_uint(f0.y);
        qah[ks][3] = __float_as_uint(f1.y);
        float2 e0 = *(const float2*)(qsl + off);
        float2 e1 = *(const float2*)(qsl + off + 8 * APS);
        qal[ks][0] = __float_as_uint(e0.x);
        qal[ks][1] = __float_as_uint(e1.x);
        qal[ks][2] = __float_as_uint(e0.y);
        qal[ks][3] = __float_as_uint(e1.y);
    }

    const int p0 = perm8(2 * t);

    // ---- phase 1: scores (b-frags pipelined one ks ahead) ----
    for (int kc = 0; kc < NCH; ++kc) {
        CP_WAIT(0);
        __syncthreads();
        if (kc + 1 < NCH) {
            stage_cp2(kvH[(kc + 1) & 1], kvL[(kc + 1) & 1],
                      Kh + (size_t)(kc + 1) * CK * DH, Kl + (size_t)(kc + 1) * CK * DH,
                      tid, DH);
            CP_COMMIT();
        }

        const float* bH = kvH[kc & 1];
        const float* bL = kvL[kc & 1];
        const int bbase = (8 * wk + g) * APS + 2 * t;
        float2 fb = *(const float2*)(bH + bbase);
        float2 fl = *(const float2*)(bL + bbase);
        float a1[4] = {}, a2[4] = {}, a3[4] = {};
#pragma unroll
        for (int ks = 0; ks < 8; ++ks) {
            unsigned bhf[2] = { __float_as_uint(fb.x), __float_as_uint(fb.y) };
            unsigned blf[2] = { __float_as_uint(fl.x), __float_as_uint(fl.y) };
            if (ks < 7) {
                fb = *(const float2*)(bH + bbase + 8 * (ks + 1));
                fl = *(const float2*)(bL + bbase + 8 * (ks + 1));
            }
            mma_tf32(a1, qah[ks], bhf);
            mma_tf32(a2, qal[ks], bhf);
            mma_tf32(a3, qah[ks], blf);
        }
        {
            const int bs = kc * CK + 8 * wk;
            const float2 mv = *(const float2*)(mrow + bs + 2 * t);
            const int q = 16 * wq + g;
            float c0 = a1[0] + a2[0] + a3[0];
            float c1 = a1[1] + a2[1] + a3[1];
            float c2 = a1[2] + a2[2] + a3[2];
            float c3 = a1[3] + a2[3] + a3[3];
            sc[q * SCP + bs + p0]           = fmaxf(fmaf(c0, SCALE, mv.x), -10000.0f);
            sc[q * SCP + bs + p0 + 2]       = fmaxf(fmaf(c1, SCALE, mv.y), -10000.0f);
            sc[(q + 8) * SCP + bs + p0]     = fmaxf(fmaf(c2, SCALE, mv.x), -10000.0f);
            sc[(q + 8) * SCP + bs + p0 + 2] = fmaxf(fmaf(c3, SCALE, mv.y), -10000.0f);
        }
    }

    stage_cp1(kvH[0], Vh, tid, SEQ);
    CP_COMMIT();
    __syncthreads();

    // ---- phase 2: Michelot sparsemax / softmax, 2 rows per warp ----
    {
        const bool sparse = ((h & 1) == 0);
        float* row0 = sc + warp * SCP;
        float* row1 = sc + (warp + 16) * SCP;
        float z0[32], z1[32];
#pragma unroll
        for (int j = 0; j < 32; ++j) { z0[j] = row0[j * 32 + lane]; z1[j] = row1[j * 32 + lane]; }
        float mx0 = -1e30f, mx1 = -1e30f;
#pragma unroll
        for (int j = 0; j < 32; ++j) { mx0 = fmaxf(mx0, z0[j]); mx1 = fmaxf(mx1, z1[j]); }
        mx0 = warpMax(mx0);
        mx1 = warpMax(mx1);

        if (sparse) {
            float tau0 = mx0 - 1.0f, tau1 = mx1 - 1.0f;
            for (int it = 0; it < 24; ++it) {
                float sa0 = 0.f, sb0 = 0.f, sc0 = 0.f, sd0 = 0.f;
                float ca0 = 0.f, cb0 = 0.f, cc0 = 0.f, cd0 = 0.f;
                float sa1 = 0.f, sb1 = 0.f, sc1 = 0.f, sd1 = 0.f;
                float ca1 = 0.f, cb1 = 0.f, cc1 = 0.f, cd1 = 0.f;
#pragma unroll
                for (int j = 0; j < 32; j += 4) {
                    if (z0[j]     > tau0) { sa0 += z0[j];     ca0 += 1.f; }
                    if (z0[j + 1] > tau0) { sb0 += z0[j + 1]; cb0 += 1.f; }
                    if (z0[j + 2] > tau0) { sc0 += z0[j + 2]; cc0 += 1.f; }
                    if (z0[j + 3] > tau0) { sd0 += z0[j + 3]; cd0 += 1.f; }
                    if (z1[j]     > tau1) { sa1 += z1[j];     ca1 += 1.f; }
                    if (z1[j + 1] > tau1) { sb1 += z1[j + 1]; cb1 += 1.f; }
                    if (z1[j + 2] > tau1) { sc1 += z1[j + 2]; cc1 += 1.f; }
                    if (z1[j + 3] > tau1) { sd1 += z1[j + 3]; cd1 += 1.f; }
                }
                float s0 = (sa0 + sb0) + (sc0 + sd0);
                float c0 = (ca0 + cb0) + (cc0 + cd0);
                float s1 = (sa1 + sb1) + (sc1 + sd1);
                float c1 = (ca1 + cb1) + (cc1 + cd1);
                s0 = warpSum(s0);
                c0 = warpSum(c0);
                s1 = warpSum(s1);
                c1 = warpSum(c1);
                const float nt0 = (s0 - 1.0f) / c0;
                const float nt1 = (s1 - 1.0f) / c1;
                const bool done = (nt0 == tau0) && (nt1 == tau1);
                tau0 = nt0;
                tau1 = nt1;
                if (done) break;
            }
#pragma unroll
            for (int j = 0; j < 32; ++j) {
                row0[j * 32 + lane] = to_tf32(fmaxf(z0[j] - tau0, 0.f));
                row1[j * 32 + lane] = to_tf32(fmaxf(z1[j] - tau1, 0.f));
            }
        } else {
            float s0 = 0.f, s1 = 0.f;
#pragma unroll
            for (int j = 0; j < 32; ++j) {
                z0[j] = __expf(z0[j] - mx0); s0 += z0[j];
                z1[j] = __expf(z1[j] - mx1); s1 += z1[j];
            }
            s0 = warpSum(s0);
            s1 = warpSum(s1);
            const float i0 = 1.0f / s0, i1 = 1.0f / s1;
#pragma unroll
            for (int j = 0; j < 32; ++j) {
                row0[j * 32 + lane] = to_tf32(z0[j] * i0);
                row1[j * 32 + lane] = to_tf32(z1[j] * i1);
            }
        }
    }

    // ---- phase 3: out = weights @ V (hi only), pipelined frag loads ----
    float o1[4] = {}, o2[4] = {};
    for (int kc = 0; kc < NCH; ++kc) {
        CP_WAIT(0);
        __syncthreads();
        if (kc + 1 < NCH) {
            stage_cp1(kvH[(kc + 1) & 1], Vh + (kc + 1) * CK, tid, SEQ);
            CP_COMMIT();
        }

        const float* bH = kvH[kc & 1];
        const float* ab = sc + (16 * wq + g) * SCP + kc * CK + 2 * t;
        const int bbase = (8 * wk + g) * APS + 2 * t;
        float2 fa0 = *(const float2*)(ab);
        float2 fa1 = *(const float2*)(ab + 8 * SCP);
        float2 fbh = *(const float2*)(bH + bbase);
#pragma unroll
        for (int kk = 0; kk < CK / 8; ++kk) {
            unsigned a[4] = { __float_as_uint(fa0.x), __float_as_uint(fa1.x),
                              __float_as_uint(fa0.y), __float_as_uint(fa1.y) };
            unsigned bhf[2] = { __float_as_uint(fbh.x), __float_as_uint(fbh.y) };
            if (kk < CK / 8 - 1) {
                fa0 = *(const float2*)(ab + 8 * (kk + 1));
                fa1 = *(const float2*)(ab + 8 * SCP + 8 * (kk + 1));
                fbh = *(const float2*)(bH + bbase + 8 * (kk + 1));   // column advance (FIXED)
            }
            mma_tf32((kk & 1) ? o2 : o1, a, bhf);
        }
    }

    // write [B, S, H*HD]
    {
        const int q = q0 + 16 * wq + g;
        float* p = out + (size_t)(b * SEQ + q) * DM + h * DH + 8 * wk + 2 * t;
        *(float2*)p = make_float2(o1[0] + o2[0], o1[1] + o2[1]);
        *(float2*)(p + 8 * DM) = make_float2(o1[2] + o2[2], o1[3] + o2[3]);
    }
}

// ---------------------------------------------------------------------------
extern "C" void kernel_launch(void* const* d_in, const int* in_sizes, int n_in,
                              void* d_out, int out_size) {
    const float* X    = (const float*)d_in[0];
    const float* Wq   = (const float*)d_in[1];
    const float* bq   = (const float*)d_in[2];
    const float* Wk   = (const float*)d_in[3];
    const float* bk   = (const float*)d_in[4];
    const float* Wv   = (const float*)d_in[5];
    const float* bv   = (const float*)d_in[6];
    const float* mask = (const float*)d_in[7];
    float* out = (float*)d_out;

    const int nsplit = (MROWS * DM + 3 * DM * DM) / 4;
    presplit_kernel<<<nsplit / 256, 256>>>(X, Wq, Wk, Wv);

    cudaFuncSetAttribute(qkv_proj_tc, cudaFuncAttributeMaxDynamicSharedMemorySize,
                         PROJ_SMEM_FLOATS * (int)sizeof(float));
    dim3 gp(DM / 128, MROWS / 128, 3);
    qkv_proj_tc<<<gp, 512, PROJ_SMEM_FLOATS * sizeof(float)>>>(bq, bk, bv);

    cudaFuncSetAttribute(attn_tc, cudaFuncAttributeMaxDynamicSharedMemorySize,
                         ATTN_SMEM_FLOATS * (int)sizeof(float));
    dim3 ga(SEQ / TQ, NH, NB);
    attn_tc<<<ga, NT, ATTN_SMEM_FLOATS * sizeof(float)>>>(mask, out);
}

// round 12
// speedup vs baseline: 1.1226x; 1.1226x over previous
#include <cuda_runtime.h>
#include <cstdint>

// Problem constants
#define NB   4
#define SEQ  1024
#define NH   16
#define DH   64
#define DM   1024
#define MROWS (NB * SEQ)

// Pre-split tf32 hi/lo copies of the GEMM inputs.
__device__ float g_xh[MROWS * DM], g_xl[MROWS * DM];
__device__ float g_wh[3 * DM * DM], g_wl[3 * DM * DM];

// Pre-split tf32 hi/lo Q/K ([B,H,S,DH], paired d-permutation) and V hi only
// ([B,H,DH,S] transposed, paired s-permutation).
__device__ float g_qh[NB * NH * SEQ * DH];
__device__ float g_ql[NB * NH * SEQ * DH];
__device__ float g_kh[NB * NH * SEQ * DH];
__device__ float g_kl[NB * NH * SEQ * DH];
__device__ float g_vh[NB * NH * SEQ * DH];

__device__ __forceinline__ int perm8(int x) { return ((x & 3) << 1) | ((x >> 2) & 1); }

__device__ __forceinline__ float to_tf32(float x) {
    unsigned u;
    asm("cvt.rna.tf32.f32 %0, %1;" : "=r"(u) : "f"(x));
    return __uint_as_float(u);
}
__device__ __forceinline__ void split_tf32(float x, float& hi, float& lo) {
    hi = to_tf32(x);
    lo = to_tf32(x - hi);
}
__device__ __forceinline__ void mma_tf32(float* c, const unsigned* a, const unsigned* b) {
    asm volatile(
        "mma.sync.aligned.m16n8k8.row.col.f32.tf32.tf32.f32 "
        "{%0,%1,%2,%3},{%4,%5,%6,%7},{%8,%9},{%0,%1,%2,%3};"
        : "+f"(c[0]), "+f"(c[1]), "+f"(c[2]), "+f"(c[3])
        : "r"(a[0]), "r"(a[1]), "r"(a[2]), "r"(a[3]), "r"(b[0]), "r"(b[1]));
}
__device__ __forceinline__ float warpMax(float v) {
#pragma unroll
    for (int o = 16; o > 0; o >>= 1) v = fmaxf(v, __shfl_xor_sync(0xffffffffu, v, o));
    return v;
}
__device__ __forceinline__ float warpSum(float v) {
#pragma unroll
    for (int o = 16; o > 0; o >>= 1) v += __shfl_xor_sync(0xffffffffu, v, o);
    return v;
}

#define CP_COMMIT() asm volatile("cp.async.commit_group;")
#define CP_WAIT(N)  asm volatile("cp.async.wait_group %0;" :: "n"(N))

__device__ __forceinline__ void cp16(float* dst, const float* src) {
    uint32_t a = (uint32_t)__cvta_generic_to_shared(dst);
    asm volatile("cp.async.cg.shared.global [%0], [%1], 16;" :: "r"(a), "l"(src));
}

// ---------------------------------------------------------------------------
// Pre-split X, Wq, Wk, Wv into tf32 hi/lo device arrays. Memory-bound.
// ---------------------------------------------------------------------------
__global__ __launch_bounds__(256) void presplit_kernel(
    const float* __restrict__ X, const float* __restrict__ Wq,
    const float* __restrict__ Wk, const float* __restrict__ Wv) {
    const size_t NX = (size_t)MROWS * DM / 4;
    const size_t NW = (size_t)DM * DM / 4;
    size_t i = (size_t)blockIdx.x * 256 + threadIdx.x;
    const float4* src;
    float4 *dh, *dl;
    size_t j;
    if (i < NX)               { src = (const float4*)X;  dh = (float4*)g_xh;      dl = (float4*)g_xl;      j = i; }
    else if (i < NX + NW)     { src = (const float4*)Wq; dh = (float4*)g_wh;      dl = (float4*)g_wl;      j = i - NX; }
    else if (i < NX + 2 * NW) { src = (const float4*)Wk; dh = (float4*)g_wh + NW; dl = (float4*)g_wl + NW; j = i - NX - NW; }
    else                      { src = (const float4*)Wv; dh = (float4*)g_wh + 2 * NW; dl = (float4*)g_wl + 2 * NW; j = i - NX - 2 * NW; }
    float4 v = src[j];
    float4 hv, lv;
    split_tf32(v.x, hv.x, lv.x); split_tf32(v.y, hv.y, lv.y);
    split_tf32(v.z, hv.z, lv.z); split_tf32(v.w, hv.w, lv.w);
    dh[j] = hv;
    dl[j] = lv;
}

// ---------------------------------------------------------------------------
// QKV projection, 3xTF32. 256 threads, 8 warps (2x4 of 64x32 warp tiles,
// the R9-proven shape), CTA tile 128x128, k-stage 16 double-buffered
// (75.8 KB smem -> TWO CTAs per SM = 16 warps/SM).
// ---------------------------------------------------------------------------
constexpr int PKS  = 16;             // k-floats per stage
constexpr int PXS  = 20;             // X row stride (banks (20g+t)%32 all distinct)
constexpr int PWS  = 136;            // W row stride (≡8 mod 32)
constexpr int XSTG = 128 * PXS;      // 2560
constexpr int WSTG = PKS * PWS;      // 2176
constexpr int STG  = 2 * XSTG + 2 * WSTG;   // 9472 floats per stage
constexpr int PROJ_SMEM_FLOATS = 2 * STG;   // 75.8 KB

__device__ __forceinline__ void proj_stage(float* s, const float* xh, const float* xl,
                                           const float* wh, const float* wl,
                                           int m0, int n0, int k0, int tid) {
    float* Xh = s;
    float* Xl = s + XSTG;
    float* Wh = s + 2 * XSTG;
    float* Wl = s + 2 * XSTG + WSTG;
#pragma unroll
    for (int it = 0; it < 2; ++it) {   // X tile 128x16 hi/lo
        const int idx = tid + 256 * it;
        const int r = idx >> 2, c = (idx & 3) << 2;
        const size_t go = (size_t)(m0 + r) * DM + k0 + c;
        cp16(Xh + r * PXS + c, xh + go);
        cp16(Xl + r * PXS + c, xl + go);
    }
#pragma unroll
    for (int it = 0; it < 2; ++it) {   // W tile 16x128 hi/lo
        const int idx = tid + 256 * it;
        const int r = idx >> 5, c = (idx & 31) << 2;
        const size_t go = (size_t)(k0 + r) * DM + n0 + c;
        cp16(Wh + r * PWS + c, wh + go);
        cp16(Wl + r * PWS + c, wl + go);
    }
}

__global__ __launch_bounds__(256, 2) void qkv_proj_tc(
    const float* __restrict__ bq, const float* __restrict__ bk,
    const float* __restrict__ bv) {
    extern __shared__ float psm[];

    const int z = blockIdx.z;
    const float* wh = g_wh + (size_t)z * DM * DM;
    const float* wl = g_wl + (size_t)z * DM * DM;
    const float* bias = (z == 0) ? bq : (z == 1) ? bk : bv;
    float* outh = (z == 0) ? g_qh : (z == 1) ? g_kh : g_vh;
    float* outl = (z == 0) ? g_ql : g_kl;     // unused for V
    const bool isV = (z == 2);

    const int tid = threadIdx.x;
    const int warp = tid >> 5, lane = tid & 31;
    const int g = lane >> 2, t = lane & 3;
    const int wm = (warp >> 2) * 64, wn = (warp & 3) * 32;
    const int m0 = blockIdx.y * 128, n0 = blockIdx.x * 128;

    float acc[4][4][4] = {};

    proj_stage(psm, g_xh, g_xl, wh, wl, m0, n0, 0, tid);
    CP_COMMIT();

    for (int kb = 0; kb < DM / PKS; ++kb) {
        CP_WAIT(0);
        __syncthreads();
        if (kb + 1 < DM / PKS) {
            proj_stage(psm + ((kb + 1) & 1) * STG, g_xh, g_xl, wh, wl,
                       m0, n0, (kb + 1) * PKS, tid);
            CP_COMMIT();
        }
        const float* Xh = psm + (kb & 1) * STG;
        const float* Xl = Xh + XSTG;
        const float* Wh = Xh + 2 * XSTG;
        const float* Wl = Xh + 2 * XSTG + WSTG;

#pragma unroll
        for (int ks = 0; ks < 2; ++ks) {
            unsigned ah[4][4], al[4][4], bh[4][2], bl[4][2];
#pragma unroll
            for (int i = 0; i < 4; ++i) {
                const int off = (wm + 16 * i + g) * PXS + 8 * ks + t;
                ah[i][0] = __float_as_uint(Xh[off]);
                ah[i][1] = __float_as_uint(Xh[off + 8 * PXS]);
                ah[i][2] = __float_as_uint(Xh[off + 4]);
                ah[i][3] = __float_as_uint(Xh[off + 8 * PXS + 4]);
                al[i][0] = __float_as_uint(Xl[off]);
                al[i][1] = __float_as_uint(Xl[off + 8 * PXS]);
                al[i][2] = __float_as_uint(Xl[off + 4]);
                al[i][3] = __float_as_uint(Xl[off + 8 * PXS + 4]);
            }
#pragma unroll
            for (int j = 0; j < 4; ++j) {
                const int off = (8 * ks + t) * PWS + wn + 8 * j + g;
                bh[j][0] = __float_as_uint(Wh[off]);
                bh[j][1] = __float_as_uint(Wh[off + 4 * PWS]);
                bl[j][0] = __float_as_uint(Wl[off]);
                bl[j][1] = __float_as_uint(Wl[off + 4 * PWS]);
            }
            // three sweeps of 16 independent MMAs
#pragma unroll
            for (int i = 0; i < 4; ++i)
#pragma unroll
                for (int j = 0; j < 4; ++j)
                    mma_tf32(acc[i][j], ah[i], bh[j]);
#pragma unroll
            for (int i = 0; i < 4; ++i)
#pragma unroll
                for (int j = 0; j < 4; ++j)
                    mma_tf32(acc[i][j], al[i], bh[j]);
#pragma unroll
            for (int i = 0; i < 4; ++i)
#pragma unroll
                for (int j = 0; j < 4; ++j)
                    mma_tf32(acc[i][j], ah[i], bl[j]);
        }
    }

    // epilogue: + bias, split, scatter into permuted layouts
#pragma unroll
    for (int j = 0; j < 4; ++j) {
        const int n = n0 + wn + 8 * j + 2 * t;
        const float b0v = bias[n], b1v = bias[n + 1];
        const int h = n >> 6, hd = n & 63;
        const int pd = (hd & ~7) | perm8(hd & 7);
#pragma unroll
        for (int i = 0; i < 4; ++i) {
            const int m = m0 + wm + 16 * i + g;
            const int bI = m >> 10, s = m & 1023;
            const int m2 = m + 8;
            const int bI2 = m2 >> 10, s2 = m2 & 1023;
            const float v0 = acc[i][j][0] + b0v;
            const float v1 = acc[i][j][1] + b1v;
            const float v2 = acc[i][j][2] + b0v;
            const float v3 = acc[i][j][3] + b1v;
            if (!isV) {
                float h0, l0, h1, l1, h2, l2, h3, l3;
                split_tf32(v0, h0, l0);
                split_tf32(v1, h1, l1);
                split_tf32(v2, h2, l2);
                split_tf32(v3, h3, l3);
                const size_t b1o = ((size_t)((bI * NH + h) * SEQ + s)) * DH;
                outh[b1o + pd] = h0;  outh[b1o + pd + 2] = h1;
                outl[b1o + pd] = l0;  outl[b1o + pd + 2] = l1;
                const size_t b2o = ((size_t)((bI2 * NH + h) * SEQ + s2)) * DH;
                outh[b2o + pd] = h2;  outh[b2o + pd + 2] = h3;
                outl[b2o + pd] = l2;  outl[b2o + pd + 2] = l3;
            } else {
                const int ps1 = (s & ~7) | perm8(s & 7);
                const int ps2 = (s2 & ~7) | perm8(s2 & 7);
                const size_t r0 = ((size_t)((bI * NH + h) * DH + hd)) * SEQ;
                const size_t r1 = ((size_t)((bI * NH + h) * DH + hd + 1)) * SEQ;
                outh[r0 + ps1] = to_tf32(v0);  outh[r1 + ps1] = to_tf32(v1);
                const size_t r0b = ((size_t)((bI2 * NH + h) * DH + hd)) * SEQ;
                const size_t r1b = ((size_t)((bI2 * NH + h) * DH + hd + 1)) * SEQ;
                outh[r0b + ps2] = to_tf32(v2);  outh[r1b + ps2] = to_tf32(v3);
            }
        }
    }
}

// ---------------------------------------------------------------------------
// Attention — R9-proven version verbatim. 512 threads, cp.async double-buffer,
// 1 barrier/chunk. Michelot sparsemax. Phase 3: w(tf32) @ V(hi).
// ---------------------------------------------------------------------------
constexpr int TQ  = 32;
constexpr int CK  = 64;
constexpr int NCH = SEQ / CK;     // 16
constexpr int NT  = 512;
constexpr int APS = 72;
constexpr int SCP = 1032;
constexpr int KVSTG = CK * APS;
constexpr int ATTN_SMEM_FLOATS = TQ * SCP + 2 * TQ * APS + 4 * KVSTG;
constexpr float SCALE = 0.125f;

__device__ __forceinline__ void stage_cp2(float* dh, float* dl,
                                          const float* gh, const float* gl,
                                          int tid, int gstride) {
#pragma unroll
    for (int it = 0; it < 2; ++it) {
        const int idx = tid + 512 * it;
        const int r = idx >> 4, c = (idx & 15) << 2;
        const int so = r * APS + c;
        const size_t go = (size_t)r * gstride + c;
        cp16(dh + so, gh + go);
        cp16(dl + so, gl + go);
    }
}
__device__ __forceinline__ void stage_cp1(float* dh, const float* gh,
                                          int tid, int gstride) {
#pragma unroll
    for (int it = 0; it < 2; ++it) {
        const int idx = tid + 512 * it;
        const int r = idx >> 4, c = (idx & 15) << 2;
        cp16(dh + r * APS + c, gh + (size_t)r * gstride + c);
    }
}

__global__ __launch_bounds__(NT, 1) void attn_tc(const float* __restrict__ mask,
                                                 float* __restrict__ out) {
    extern __shared__ float sm[];
    float* sc  = sm;                    // [TQ][SCP]
    float* qsh = sm + TQ * SCP;         // [TQ][APS]
    float* qsl = qsh + TQ * APS;
    float* kv  = qsl + TQ * APS;

    float* kvH[2] = { kv, kv + 2 * KVSTG };
    float* kvL[2] = { kv + KVSTG, kv + 3 * KVSTG };

    const int tid = threadIdx.x;
    const int b = blockIdx.z, h = blockIdx.y;
    const int q0 = blockIdx.x * TQ;
    const int bh_i = b * NH + h;
    const float* Qh = g_qh + ((size_t)bh_i * SEQ + q0) * DH;
    const float* Ql = g_ql + ((size_t)bh_i * SEQ + q0) * DH;
    const float* Kh = g_kh + (size_t)bh_i * SEQ * DH;
    const float* Kl = g_kl + (size_t)bh_i * SEQ * DH;
    const float* Vh = g_vh + (size_t)bh_i * DH * SEQ;
    const float* mrow = mask + b * SEQ;

    const int warp = tid >> 5, lane = tid & 31;
    const int g = lane >> 2, t = lane & 3;
    const int wq = warp >> 3;
    const int wk = warp & 7;

    stage_cp2(kvH[0], kvL[0], Kh, Kl, tid, DH);
    CP_COMMIT();
    {
        const int e = tid << 2;
        const int qi = e >> 6, dd = e & 63;
        *(float4*)(qsh + qi * APS + dd) = *(const float4*)(Qh + e);
        *(float4*)(qsl + qi * APS + dd) = *(const float4*)(Ql + e);
    }
    __syncthreads();

    unsigned qah[8][4], qal[8][4];
#pragma unroll
    for (int ks = 0; ks < 8; ++ks) {
        const int off = (16 * wq + g) * APS + 8 * ks + 2 * t;
        float2 f0 = *(const float2*)(qsh + off);
        float2 f1 = *(const float2*)(qsh + off + 8 * APS);
        qah[ks][0] = __float_as_uint(f0.x);
        qah[ks][1] = __float_as_uint(f1.x);
        qah[ks][2] = __float_as_uint(f0.y);
        qah[ks][3] = __float_as_uint(f1.y);
        float2 e0 = *(const float2*)(qsl + off);
        float2 e1 = *(const float2*)(qsl + off + 8 * APS);
        qal[ks][0] = __float_as_uint(e0.x);
        qal[ks][1] = __float_as_uint(e1.x);
        qal[ks][2] = __float_as_uint(e0.y);
        qal[ks][3] = __float_as_uint(e1.y);
    }

    const int p0 = perm8(2 * t);

    // ---- phase 1: scores ----
    for (int kc = 0; kc < NCH; ++kc) {
        CP_WAIT(0);
        __syncthreads();
        if (kc + 1 < NCH) {
            stage_cp2(kvH[(kc + 1) & 1], kvL[(kc + 1) & 1],
                      Kh + (size_t)(kc + 1) * CK * DH, Kl + (size_t)(kc + 1) * CK * DH,
                      tid, DH);
            CP_COMMIT();
        }

        const float* bH = kvH[kc & 1];
        const float* bL = kvL[kc & 1];
        float a1[4] = {}, a2[4] = {}, a3[4] = {};
#pragma unroll
        for (int ks = 0; ks < 8; ++ks) {
            const int boff = (8 * wk + g) * APS + 8 * ks + 2 * t;
            float2 fb = *(const float2*)(bH + boff);
            float2 fl = *(const float2*)(bL + boff);
            unsigned bhf[2] = { __float_as_uint(fb.x), __float_as_uint(fb.y) };
            unsigned blf[2] = { __float_as_uint(fl.x), __float_as_uint(fl.y) };
            mma_tf32(a1, qah[ks], bhf);
            mma_tf32(a2, qal[ks], bhf);
            mma_tf32(a3, qah[ks], blf);
        }
        {
            const int bs = kc * CK + 8 * wk;
            const float2 mv = *(const float2*)(mrow + bs + 2 * t);
            const int q = 16 * wq + g;
            float c0 = a1[0] + a2[0] + a3[0];
            float c1 = a1[1] + a2[1] + a3[1];
            float c2 = a1[2] + a2[2] + a3[2];
            float c3 = a1[3] + a2[3] + a3[3];
            sc[q * SCP + bs + p0]           = fmaxf(fmaf(c0, SCALE, mv.x), -10000.0f);
            sc[q * SCP + bs + p0 + 2]       = fmaxf(fmaf(c1, SCALE, mv.y), -10000.0f);
            sc[(q + 8) * SCP + bs + p0]     = fmaxf(fmaf(c2, SCALE, mv.x), -10000.0f);
            sc[(q + 8) * SCP + bs + p0 + 2] = fmaxf(fmaf(c3, SCALE, mv.y), -10000.0f);
        }
    }

    stage_cp1(kvH[0], Vh, tid, SEQ);
    CP_COMMIT();
    __syncthreads();

    // ---- phase 2: Michelot sparsemax / softmax, 2 rows per warp ----
    {
        const bool sparse = ((h & 1) == 0);
        float* row0 = sc + warp * SCP;
        float* row1 = sc + (warp + 16) * SCP;
        float z0[32], z1[32];
#pragma unroll
        for (int j = 0; j < 32; ++j) { z0[j] = row0[j * 32 + lane]; z1[j] = row1[j * 32 + lane]; }
        float mx0 = -1e30f, mx1 = -1e30f;
#pragma unroll
        for (int j = 0; j < 32; ++j) { mx0 = fmaxf(mx0, z0[j]); mx1 = fmaxf(mx1, z1[j]); }
        mx0 = warpMax(mx0);
        mx1 = warpMax(mx1);

        if (sparse) {
            float tau0 = mx0 - 1.0f, tau1 = mx1 - 1.0f;
            for (int it = 0; it < 24; ++it) {
                float sa0 = 0.f, sb0 = 0.f, sc0 = 0.f, sd0 = 0.f;
                float ca0 = 0.f, cb0 = 0.f, cc0 = 0.f, cd0 = 0.f;
                float sa1 = 0.f, sb1 = 0.f, sc1 = 0.f, sd1 = 0.f;
                float ca1 = 0.f, cb1 = 0.f, cc1 = 0.f, cd1 = 0.f;
#pragma unroll
                for (int j = 0; j < 32; j += 4) {
                    if (z0[j]     > tau0) { sa0 += z0[j];     ca0 += 1.f; }
                    if (z0[j + 1] > tau0) { sb0 += z0[j + 1]; cb0 += 1.f; }
                    if (z0[j + 2] > tau0) { sc0 += z0[j + 2]; cc0 += 1.f; }
                    if (z0[j + 3] > tau0) { sd0 += z0[j + 3]; cd0 += 1.f; }
                    if (z1[j]     > tau1) { sa1 += z1[j];     ca1 += 1.f; }
                    if (z1[j + 1] > tau1) { sb1 += z1[j + 1]; cb1 += 1.f; }
                    if (z1[j + 2] > tau1) { sc1 += z1[j + 2]; cc1 += 1.f; }
                    if (z1[j + 3] > tau1) { sd1 += z1[j + 3]; cd1 += 1.f; }
                }
                float s0 = (sa0 + sb0) + (sc0 + sd0);
                float c0 = (ca0 + cb0) + (cc0 + cd0);
                float s1 = (sa1 + sb1) + (sc1 + sd1);
                float c1 = (ca1 + cb1) + (cc1 + cd1);
                s0 = warpSum(s0);
                c0 = warpSum(c0);
                s1 = warpSum(s1);
                c1 = warpSum(c1);
                const float nt0 = (s0 - 1.0f) / c0;
                const float nt1 = (s1 - 1.0f) / c1;
                const bool done = (nt0 == tau0) && (nt1 == tau1);
                tau0 = nt0;
                tau1 = nt1;
                if (done) break;
            }
#pragma unroll
            for (int j = 0; j < 32; ++j) {
                row0[j * 32 + lane] = to_tf32(fmaxf(z0[j] - tau0, 0.f));
                row1[j * 32 + lane] = to_tf32(fmaxf(z1[j] - tau1, 0.f));
            }
        } else {
            float s0 = 0.f, s1 = 0.f;
#pragma unroll
            for (int j = 0; j < 32; ++j) {
                z0[j] = __expf(z0[j] - mx0); s0 += z0[j];
                z1[j] = __expf(z1[j] - mx1); s1 += z1[j];
            }
            s0 = warpSum(s0);
            s1 = warpSum(s1);
            const float i0 = 1.0f / s0, i1 = 1.0f / s1;
#pragma unroll
            for (int j = 0; j < 32; ++j) {
                row0[j * 32 + lane] = to_tf32(z0[j] * i0);
                row1[j * 32 + lane] = to_tf32(z1[j] * i1);
            }
        }
    }

    // ---- phase 3: out = weights @ V (hi only), 2 accumulator chains ----
    float o1[4] = {}, o2[4] = {};
    for (int kc = 0; kc < NCH; ++kc) {
        CP_WAIT(0);
        __syncthreads();
        if (kc + 1 < NCH) {
            stage_cp1(kvH[(kc + 1) & 1], Vh + (kc + 1) * CK, tid, SEQ);
            CP_COMMIT();
        }

        const float* bH = kvH[kc & 1];
#pragma unroll
        for (int kk = 0; kk < CK / 8; ++kk) {
            const float* ap = sc + (16 * wq + g) * SCP + kc * CK + 8 * kk + 2 * t;
            float2 fa0 = *(const float2*)(ap);
            float2 fa1 = *(const float2*)(ap + 8 * SCP);
            unsigned a[4] = { __float_as_uint(fa0.x), __float_as_uint(fa1.x),
                              __float_as_uint(fa0.y), __float_as_uint(fa1.y) };
            const int boff = (8 * wk + g) * APS + 8 * kk + 2 * t;
            float2 fbh = *(const float2*)(bH + boff);
            unsigned bhf[2] = { __float_as_uint(fbh.x), __float_as_uint(fbh.y) };
            mma_tf32((kk & 1) ? o2 : o1, a, bhf);
        }
    }

    // write [B, S, H*HD]
    {
        const int q = q0 + 16 * wq + g;
        float* p = out + (size_t)(b * SEQ + q) * DM + h * DH + 8 * wk + 2 * t;
        *(float2*)p = make_float2(o1[0] + o2[0], o1[1] + o2[1]);
        *(float2*)(p + 8 * DM) = make_float2(o1[2] + o2[2], o1[3] + o2[3]);
    }
}

// ---------------------------------------------------------------------------
extern "C" void kernel_launch(void* const* d_in, const int* in_sizes, int n_in,
                              void* d_out, int out_size) {
    const float* X    = (const float*)d_in[0];
    const float* Wq   = (const float*)d_in[1];
    const float* bq   = (const float*)d_in[2];
    const float* Wk   = (const float*)d_in[3];
    const float* bk   = (const float*)d_in[4];
    const float* Wv   = (const float*)d_in[5];
    const float* bv   = (const float*)d_in[6];
    const float* mask = (const float*)d_in[7];
    float* out = (float*)d_out;

    const int nsplit = (MROWS * DM + 3 * DM * DM) / 4;
    presplit_kernel<<<nsplit / 256, 256>>>(X, Wq, Wk, Wv);

    cudaFuncSetAttribute(qkv_proj_tc, cudaFuncAttributeMaxDynamicSharedMemorySize,
                         PROJ_SMEM_FLOATS * (int)sizeof(float));
    dim3 gp(DM / 128, MROWS / 128, 3);
    qkv_proj_tc<<<gp, 256, PROJ_SMEM_FLOATS * sizeof(float)>>>(bq, bk, bv);

    cudaFuncSetAttribute(attn_tc, cudaFuncAttributeMaxDynamicSharedMemorySize,
                         ATTN_SMEM_FLOATS * (int)sizeof(float));
    dim3 ga(SEQ / TQ, NH, NB);
    attn_tc<<<ga, NT, ATTN_SMEM_FLOATS * sizeof(float)>>>(mask, out);
}